// round 4
// baseline (speedup 1.0000x reference)
#include <cuda_runtime.h>
#include <math.h>

// ---------------------------------------------------------------------------
// VQ-VAE forward, fp32. Conv: co-group register blocking, k-major smem weights
// (float4 broadcast loads). Deconv: 2x2 output-quad threads.
// ---------------------------------------------------------------------------

#define BB 64
static const float BN_EPS = 1e-5f;

// ------------------------- scratch (device globals) ------------------------
__device__ float g_a1[64 * 16 * 128 * 128];
__device__ float g_a2[64 * 32 * 64 * 64];
__device__ float g_a3[64 * 64 * 32 * 32];
__device__ float g_q [64 * 64 * 32 * 32];
__device__ float g_d1[64 * 32 * 64 * 64];
__device__ float g_d2[64 * 16 * 128 * 128];

__device__ int    g_idx[65536];
__device__ float  g_codeNorm[512];
__device__ float2 g_part[64 * 32];
__device__ float  g_scale[64];
__device__ float  g_shift[64];
__device__ float  g_lossPart[512];

// ------------------------------ conv k4 s2 p1 ------------------------------
// One thread = one output pixel (n,y,x) x COUTG channels.
// Weights staged k-major: ws[(cil*16+tap)][co]  -> float4 broadcast loads.
template <int CIN, int COUT, int COUTG, int CICHUNK, int HIN, int WIN>
__global__ __launch_bounds__(256)
void conv_k(const float* __restrict__ in, const float* __restrict__ w,
            const float* __restrict__ bias, float* __restrict__ out)
{
    constexpr int HOUT = HIN / 2, WOUT = WIN / 2;
    __shared__ __align__(16) float ws[CICHUNK * 16 * COUTG];

    const int p = blockIdx.x * 256 + threadIdx.x;
    const int x = p % WOUT;
    const int y = (p / WOUT) % HOUT;
    const int n = p / (WOUT * HOUT);
    const int cog = blockIdx.y * COUTG;

    float acc[COUTG];
    #pragma unroll
    for (int j = 0; j < COUTG; j++) acc[j] = __ldg(&bias[cog + j]);

    const int y0 = 2 * y - 1;
    const int x0 = 2 * x - 1;
    const float* inn = in + (long long)n * CIN * HIN * WIN;

    for (int ci0 = 0; ci0 < CIN; ci0 += CICHUNK) {
        __syncthreads();
        for (int t = threadIdx.x; t < COUTG * CICHUNK * 16; t += 256) {
            const int j  = t % COUTG;
            const int kk = t / COUTG;           // cil*16 + tap
            ws[t] = w[(cog + j) * CIN * 16 + ci0 * 16 + kk];
        }
        __syncthreads();

        #pragma unroll
        for (int cil = 0; cil < CICHUNK; cil++) {
            const float* chan = inn + (long long)(ci0 + cil) * HIN * WIN;
            float tap[16];
            #pragma unroll
            for (int ky = 0; ky < 4; ky++) {
                const int yi = y0 + ky;
                const bool vy = ((unsigned)yi < (unsigned)HIN);
                const float* row = chan + yi * WIN;
                #pragma unroll
                for (int kx = 0; kx < 4; kx++) {
                    const int xi = x0 + kx;
                    const bool ok = vy && ((unsigned)xi < (unsigned)WIN);
                    tap[ky * 4 + kx] = ok ? __ldg(&row[xi]) : 0.f;
                }
            }
            #pragma unroll
            for (int k = 0; k < 16; k++) {
                const float tv = tap[k];
                const float4* w4 = (const float4*)&ws[(cil * 16 + k) * COUTG];
                #pragma unroll
                for (int j4 = 0; j4 < COUTG / 4; j4++) {
                    const float4 ww = w4[j4];
                    acc[4*j4+0] = fmaf(tv, ww.x, acc[4*j4+0]);
                    acc[4*j4+1] = fmaf(tv, ww.y, acc[4*j4+1]);
                    acc[4*j4+2] = fmaf(tv, ww.z, acc[4*j4+2]);
                    acc[4*j4+3] = fmaf(tv, ww.w, acc[4*j4+3]);
                }
            }
        }
    }

    #pragma unroll
    for (int j = 0; j < COUTG; j++)
        out[(((long long)n * COUT + cog + j) * HOUT + y) * WOUT + x] = acc[j];
}

// --------------------------- deconv k4 s2 p1 -------------------------------
// One thread = one 2x2 OUTPUT QUAD (2Y..2Y+1, 2X..2X+1) x COUTG channels.
// Input patch 3x3 around (Y,X). Weight (ky,kx): output parity (ky&1, kx&1),
// input offset r=(ky>>1)+(ky&1), c=(kx>>1)+(kx&1).
// COUTG_PAD >= COUTG, multiple of 4 (pad for COUT=3).
template <int CIN, int COUT, int COUTG, int COUTG_PAD, int CICHUNK, int HIN, int WIN>
__global__ __launch_bounds__(256)
void deconv_k(const float* __restrict__ in, const float* __restrict__ w,
              const float* __restrict__ bias, float* __restrict__ out)
{
    constexpr int HOUT = HIN * 2, WOUT = WIN * 2;
    __shared__ __align__(16) float ws[CICHUNK * 16 * COUTG_PAD];

    const int p = blockIdx.x * 256 + threadIdx.x;   // quad index
    const int X = p % WIN;
    const int Y = (p / WIN) % HIN;
    const int n = p / (WIN * HIN);
    const int cog = blockIdx.y * COUTG;

    float acc[4][COUTG_PAD];
    #pragma unroll
    for (int j = 0; j < COUTG_PAD; j++) {
        const float b = (cog + j < COUT) ? __ldg(&bias[cog + j]) : 0.f;
        acc[0][j] = b; acc[1][j] = b; acc[2][j] = b; acc[3][j] = b;
    }

    const float* inn = in + (long long)n * CIN * HIN * WIN;

    for (int ci0 = 0; ci0 < CIN; ci0 += CICHUNK) {
        __syncthreads();
        for (int t = threadIdx.x; t < COUTG_PAD * CICHUNK * 16; t += 256) {
            const int j  = t % COUTG_PAD;
            const int kk = t / COUTG_PAD;
            ws[t] = (cog + j < COUT) ? w[(cog + j) * CIN * 16 + ci0 * 16 + kk] : 0.f;
        }
        __syncthreads();

        #pragma unroll
        for (int cil = 0; cil < CICHUNK; cil++) {
            const float* chan = inn + (long long)(ci0 + cil) * HIN * WIN;
            float tv[3][3];
            #pragma unroll
            for (int r = 0; r < 3; r++) {
                const int yi = Y - 1 + r;
                const bool vy = ((unsigned)yi < (unsigned)HIN);
                #pragma unroll
                for (int c = 0; c < 3; c++) {
                    const int xi = X - 1 + c;
                    const bool ok = vy && ((unsigned)xi < (unsigned)WIN);
                    tv[r][c] = ok ? __ldg(&chan[yi * WIN + xi]) : 0.f;
                }
            }
            #pragma unroll
            for (int ky = 0; ky < 4; ky++) {
                #pragma unroll
                for (int kx = 0; kx < 4; kx++) {
                    const int py = ky & 1, px = kx & 1;
                    const int r = (ky >> 1) + py;
                    const int c = (kx >> 1) + px;
                    const float t = tv[r][c];
                    const int o = py * 2 + px;
                    const float4* w4 =
                        (const float4*)&ws[(cil * 16 + ky * 4 + kx) * COUTG_PAD];
                    #pragma unroll
                    for (int j4 = 0; j4 < COUTG_PAD / 4; j4++) {
                        const float4 ww = w4[j4];
                        acc[o][4*j4+0] = fmaf(t, ww.x, acc[o][4*j4+0]);
                        acc[o][4*j4+1] = fmaf(t, ww.y, acc[o][4*j4+1]);
                        acc[o][4*j4+2] = fmaf(t, ww.z, acc[o][4*j4+2]);
                        acc[o][4*j4+3] = fmaf(t, ww.w, acc[o][4*j4+3]);
                    }
                }
            }
        }
    }

    #pragma unroll
    for (int j = 0; j < COUTG; j++) {
        const long long cb = (long long)n * COUT + cog + j;
        float2* row0 = (float2*)out + (cb * HOUT + 2 * Y) * (WOUT / 2) + X;
        float2* row1 = (float2*)out + (cb * HOUT + 2 * Y + 1) * (WOUT / 2) + X;
        *row0 = make_float2(acc[0][j], acc[1][j]);
        *row1 = make_float2(acc[2][j], acc[3][j]);
    }
}

// ------------------------------- batchnorm ---------------------------------
__global__ __launch_bounds__(256)
void bn_stats(const float* __restrict__ x, int C, int HW)
{
    const int c = blockIdx.x >> 5;
    const int s = blockIdx.x & 31;
    const int chunk4 = HW >> 7;

    float sum = 0.f, sq = 0.f;
    for (int n = 0; n < BB; n++) {
        const float4* base = (const float4*)(x + ((long long)(n * C + c)) * HW) +
                             s * chunk4;
        for (int p = threadIdx.x; p < chunk4; p += 256) {
            float4 v = base[p];
            sum += v.x + v.y + v.z + v.w;
            sq = fmaf(v.x, v.x, sq); sq = fmaf(v.y, v.y, sq);
            sq = fmaf(v.z, v.z, sq); sq = fmaf(v.w, v.w, sq);
        }
    }
    __shared__ float s1[256], s2[256];
    s1[threadIdx.x] = sum; s2[threadIdx.x] = sq;
    __syncthreads();
    for (int off = 128; off; off >>= 1) {
        if (threadIdx.x < off) {
            s1[threadIdx.x] += s1[threadIdx.x + off];
            s2[threadIdx.x] += s2[threadIdx.x + off];
        }
        __syncthreads();
    }
    if (threadIdx.x == 0) g_part[blockIdx.x] = make_float2(s1[0], s2[0]);
}

__global__ void bn_finalize(const float* __restrict__ gam,
                            const float* __restrict__ bet, int HW)
{
    const int c = blockIdx.x;
    float2 p = g_part[c * 32 + threadIdx.x];
    double S = p.x, Q = p.y;
    for (int off = 16; off; off >>= 1) {
        S += __shfl_down_sync(0xffffffffu, S, off);
        Q += __shfl_down_sync(0xffffffffu, Q, off);
    }
    if (threadIdx.x == 0) {
        const double P = (double)BB * (double)HW;
        const double mean = S / P;
        const double var  = Q / P - mean * mean;
        const float rstd  = (float)(1.0 / sqrt(var + (double)BN_EPS));
        const float sc = gam[c] * rstd;
        g_scale[c] = sc;
        g_shift[c] = bet[c] - (float)mean * sc;
    }
}

template <int MODE>
__global__ __launch_bounds__(256)
void bn_apply(float* __restrict__ x, int C, int HW, int total4)
{
    const int i = blockIdx.x * 256 + threadIdx.x;
    if (i >= total4) return;
    const int hw4 = HW >> 2;
    const int c = (i / hw4) % C;
    const float sc = g_scale[c], sh = g_shift[c];
    float4 v = ((float4*)x)[i];
    v.x = fmaf(v.x, sc, sh); v.y = fmaf(v.y, sc, sh);
    v.z = fmaf(v.z, sc, sh); v.w = fmaf(v.w, sc, sh);
    if (MODE == 0) {
        v.x = fmaxf(v.x, 0.f); v.y = fmaxf(v.y, 0.f);
        v.z = fmaxf(v.z, 0.f); v.w = fmaxf(v.w, 0.f);
    } else {
        v.x = tanhf(v.x); v.y = tanhf(v.y);
        v.z = tanhf(v.z); v.w = tanhf(v.w);
    }
    ((float4*)x)[i] = v;
}

// ---------------------------------- VQ -------------------------------------
__global__ void code_norms(const float* __restrict__ cb)
{
    const int k = threadIdx.x;
    float s = 0.f;
    const float* r = cb + k * 64;
    #pragma unroll
    for (int d = 0; d < 64; d++) s = fmaf(r[d], r[d], s);
    g_codeNorm[k] = s;
}

__global__ __launch_bounds__(128)
void vq_argmin(const float* __restrict__ ze, const float* __restrict__ cb)
{
    __shared__ float sc[64 * 64];
    __shared__ float scn[64];
    __shared__ float red[128];

    const int idx = blockIdx.x * 128 + threadIdx.x;
    const int n  = idx >> 10;
    const int hw = idx & 1023;
    const float* base = ze + (long long)n * 64 * 1024 + hw;

    float z[64];
    #pragma unroll
    for (int d = 0; d < 64; d++) z[d] = base[d * 1024];
    float zz = 0.f;
    #pragma unroll
    for (int d = 0; d < 64; d++) zz = fmaf(z[d], z[d], zz);

    float best = 3.4e38f;
    int   bi   = 0;
    for (int ch = 0; ch < 8; ch++) {
        __syncthreads();
        for (int t = threadIdx.x; t < 1024; t += 128)
            ((float4*)sc)[t] = ((const float4*)(cb + ch * 4096))[t];
        if (threadIdx.x < 64) scn[threadIdx.x] = g_codeNorm[ch * 64 + threadIdx.x];
        __syncthreads();
        #pragma unroll 2
        for (int j = 0; j < 64; j++) {
            const float4* cp = (const float4*)&sc[j * 64];
            float dot = 0.f;
            #pragma unroll
            for (int d4 = 0; d4 < 16; d4++) {
                float4 c4 = cp[d4];
                dot = fmaf(z[4*d4+0], c4.x, dot);
                dot = fmaf(z[4*d4+1], c4.y, dot);
                dot = fmaf(z[4*d4+2], c4.z, dot);
                dot = fmaf(z[4*d4+3], c4.w, dot);
            }
            const float dist = zz - 2.f * dot + scn[j];
            const int k = ch * 64 + j;
            if (dist < best) { best = dist; bi = k; }
        }
    }
    g_idx[idx] = bi;

    const float* cr = cb + bi * 64;
    float e = 0.f;
    #pragma unroll
    for (int d = 0; d < 64; d++) { float df = z[d] - cr[d]; e = fmaf(df, df, e); }

    red[threadIdx.x] = e;
    __syncthreads();
    for (int off = 64; off; off >>= 1) {
        if (threadIdx.x < off) red[threadIdx.x] += red[threadIdx.x + off];
        __syncthreads();
    }
    if (threadIdx.x == 0) g_lossPart[blockIdx.x] = red[0];
}

__global__ void vq_loss_final(float* __restrict__ loss_out)
{
    __shared__ double red[512];
    red[threadIdx.x] = (double)g_lossPart[threadIdx.x];
    __syncthreads();
    for (int off = 256; off; off >>= 1) {
        if (threadIdx.x < off) red[threadIdx.x] += red[threadIdx.x + off];
        __syncthreads();
    }
    if (threadIdx.x == 0)
        loss_out[0] = (float)(2.0 * red[0] / (65536.0 * 64.0));
}

__global__ __launch_bounds__(256)
void vq_scatter(float* __restrict__ q, const float* __restrict__ cb)
{
    const int i = blockIdx.x * 256 + threadIdx.x;
    const int hw = i & 1023;
    const int d  = (i >> 10) & 63;
    const int n  = i >> 16;
    const int code = g_idx[n * 1024 + hw];
    q[i] = cb[code * 64 + d];
}

// -------------------------------- launch -----------------------------------
static inline int nblk(long long total) { return (int)((total + 255) / 256); }

extern "C" void kernel_launch(void* const* d_in, const int* in_sizes, int n_in,
                              void* d_out, int out_size)
{
    (void)in_sizes; (void)n_in;
    const float* x    = (const float*)d_in[0];
    const float* cb   = (const float*)d_in[1];
    const float* eW1  = (const float*)d_in[2];
    const float* eb1  = (const float*)d_in[3];
    const float* eg1  = (const float*)d_in[4];
    const float* ebt1 = (const float*)d_in[5];
    const float* eW2  = (const float*)d_in[6];
    const float* eb2  = (const float*)d_in[7];
    const float* eg2  = (const float*)d_in[8];
    const float* ebt2 = (const float*)d_in[9];
    const float* eW3  = (const float*)d_in[10];
    const float* eb3  = (const float*)d_in[11];
    const float* eg3  = (const float*)d_in[12];
    const float* ebt3 = (const float*)d_in[13];
    const float* dW1  = (const float*)d_in[14];
    const float* db1  = (const float*)d_in[15];
    const float* dg1  = (const float*)d_in[16];
    const float* dbt1 = (const float*)d_in[17];
    const float* dW2  = (const float*)d_in[18];
    const float* db2  = (const float*)d_in[19];
    const float* dg2  = (const float*)d_in[20];
    const float* dbt2 = (const float*)d_in[21];
    const float* dW3  = (const float*)d_in[22];
    const float* db3  = (const float*)d_in[23];
    const float* dg3  = (const float*)d_in[24];
    const float* dbt3 = (const float*)d_in[25];
    float* out = (float*)d_out;

    float *a1, *a2, *a3, *q, *d1, *d2;
    cudaGetSymbolAddress((void**)&a1, g_a1);
    cudaGetSymbolAddress((void**)&a2, g_a2);
    cudaGetSymbolAddress((void**)&a3, g_a3);
    cudaGetSymbolAddress((void**)&q,  g_q);
    cudaGetSymbolAddress((void**)&d1, g_d1);
    cudaGetSymbolAddress((void**)&d2, g_d2);

    // ---------------- encoder ----------------
    {   // conv1: 3->16, 256->128
        const long long T = (long long)BB * 16 * 128 * 128;
        dim3 grid(1048576 / 256, 1);
        conv_k<3, 16, 16, 3, 256, 256><<<grid, 256>>>(x, eW1, eb1, a1);
        bn_stats<<<16 * 32, 256>>>(a1, 16, 128 * 128);
        bn_finalize<<<16, 32>>>(eg1, ebt1, 128 * 128);
        bn_apply<0><<<nblk(T / 4), 256>>>(a1, 16, 128 * 128, (int)(T / 4));
    }
    {   // conv2: 16->32, 128->64 (single weight chunk, 32KB smem)
        const long long T = (long long)BB * 32 * 64 * 64;
        dim3 grid(262144 / 256, 1);
        conv_k<16, 32, 32, 16, 128, 128><<<grid, 256>>>(a1, eW2, eb2, a2);
        bn_stats<<<32 * 32, 256>>>(a2, 32, 64 * 64);
        bn_finalize<<<32, 32>>>(eg2, ebt2, 64 * 64);
        bn_apply<0><<<nblk(T / 4), 256>>>(a2, 32, 64 * 64, (int)(T / 4));
    }
    {   // conv3: 32->64, 64->32, 2 co-groups, 2 ci chunks
        const long long T = (long long)BB * 64 * 32 * 32;
        dim3 grid(65536 / 256, 2);
        conv_k<32, 64, 32, 16, 64, 64><<<grid, 256>>>(a2, eW3, eb3, a3);
        bn_stats<<<64 * 32, 256>>>(a3, 64, 32 * 32);
        bn_finalize<<<64, 32>>>(eg3, ebt3, 32 * 32);
        bn_apply<0><<<nblk(T / 4), 256>>>(a3, 64, 32 * 32, (int)(T / 4));
    }

    // ---------------- vector quantization ----------------
    code_norms<<<1, 512>>>(cb);
    vq_argmin<<<512, 128>>>(a3, cb);
    vq_loss_final<<<1, 512>>>(out + (out_size - 1));
    vq_scatter<<<nblk((long long)BB * 64 * 32 * 32), 256>>>(q, cb);

    // ---------------- decoder ----------------
    {   // deconv1: 64->32 (quads: 64*32*32=65536), COUTG=16 x2 groups
        const long long T = (long long)BB * 32 * 64 * 64;
        dim3 grid(65536 / 256, 2);
        deconv_k<64, 32, 16, 16, 32, 32, 32><<<grid, 256>>>(q, dW1, db1, d1);
        bn_stats<<<32 * 32, 256>>>(d1, 32, 64 * 64);
        bn_finalize<<<32, 32>>>(dg1, dbt1, 64 * 64);
        bn_apply<0><<<nblk(T / 4), 256>>>(d1, 32, 64 * 64, (int)(T / 4));
    }
    {   // deconv2: 32->16 (quads: 64*64*64=262144), single chunk 32KB
        const long long T = (long long)BB * 16 * 128 * 128;
        dim3 grid(262144 / 256, 1);
        deconv_k<32, 16, 16, 16, 32, 64, 64><<<grid, 256>>>(d1, dW2, db2, d2);
        bn_stats<<<16 * 32, 256>>>(d2, 16, 128 * 128);
        bn_finalize<<<16, 32>>>(dg2, dbt2, 128 * 128);
        bn_apply<0><<<nblk(T / 4), 256>>>(d2, 16, 128 * 128, (int)(T / 4));
    }
    {   // deconv3: 16->3 (quads: 64*128*128=1048576), pad channels to 4
        const long long T = (long long)BB * 3 * 256 * 256;
        dim3 grid(1048576 / 256, 1);
        deconv_k<16, 3, 3, 4, 16, 128, 128><<<grid, 256>>>(d2, dW3, db3, out);
        bn_stats<<<3 * 32, 256>>>(out, 3, 256 * 256);
        bn_finalize<<<3, 32>>>(dg3, dbt3, 256 * 256);
        bn_apply<1><<<nblk(T / 4), 256>>>(out, 3, 256 * 256, (int)T / 4);
    }
}

// round 5
// speedup vs baseline: 1.0897x; 1.0897x over previous
#include <cuda_runtime.h>
#include <math.h>

// ---------------------------------------------------------------------------
// VQ-VAE forward, fp32. Conv/deconv with SMEM input tiling (16x16 spatial
// tiles), k-major smem weights (float4 broadcast), deconv as 2x2 quads.
// ---------------------------------------------------------------------------

#define BB 64
static const float BN_EPS = 1e-5f;

// ------------------------- scratch (device globals) ------------------------
__device__ float g_a1[64 * 16 * 128 * 128];
__device__ float g_a2[64 * 32 * 64 * 64];
__device__ float g_a3[64 * 64 * 32 * 32];
__device__ float g_q [64 * 64 * 32 * 32];
__device__ float g_d1[64 * 32 * 64 * 64];
__device__ float g_d2[64 * 16 * 128 * 128];

__device__ int    g_idx[65536];
__device__ float  g_codeNorm[512];
__device__ float2 g_part[64 * 32];
__device__ float  g_scale[64];
__device__ float  g_shift[64];
__device__ float  g_lossPart[512];

// ------------------------------ conv k4 s2 p1 ------------------------------
// Block = 16x16 output tile of one image. Input patch 34x34 per channel staged
// in smem per ci-chunk. COUTG output channels per thread (grid.y groups).
template <int CIN, int COUT, int COUTG, int CICHUNK, int HIN, int WIN>
__global__ __launch_bounds__(256)
void conv_t(const float* __restrict__ in, const float* __restrict__ w,
            const float* __restrict__ bias, float* __restrict__ out)
{
    constexpr int HOUT = HIN / 2, WOUT = WIN / 2;
    constexpr int NBX = WOUT / 16, NBY = HOUT / 16;
    constexpr int TIN = 34, TP = 36;

    __shared__ float tile[CICHUNK][TIN][TP];
    __shared__ __align__(16) float ws[CICHUNK * 16 * COUTG];

    const int b  = blockIdx.x;
    const int tx = b % NBX;
    const int ty = (b / NBX) % NBY;
    const int n  = b / (NBX * NBY);
    const int cog = blockIdx.y * COUTG;
    const int lx = threadIdx.x & 15, ly = threadIdx.x >> 4;

    const int X0 = tx * 32 - 1, Y0 = ty * 32 - 1;
    const float* inn = in + (long long)n * CIN * HIN * WIN;

    float acc[COUTG];
    #pragma unroll
    for (int j = 0; j < COUTG; j++) acc[j] = __ldg(&bias[cog + j]);

    for (int ci0 = 0; ci0 < CIN; ci0 += CICHUNK) {
        __syncthreads();
        for (int t = threadIdx.x; t < COUTG * CICHUNK * 16; t += 256) {
            const int j  = t % COUTG;
            const int kk = t / COUTG;
            ws[t] = w[(cog + j) * CIN * 16 + ci0 * 16 + kk];
        }
        for (int t = threadIdx.x; t < CICHUNK * TIN * 34; t += 256) {
            const int c  = t / (TIN * 34);
            const int r  = (t / 34) % TIN;
            const int cc = t % 34;
            const int gy = Y0 + r, gx = X0 + cc;
            const bool ok = ((unsigned)gy < (unsigned)HIN) &&
                            ((unsigned)gx < (unsigned)WIN);
            tile[c][r][cc] = ok ?
                __ldg(&inn[((long long)(ci0 + c) * HIN + gy) * WIN + gx]) : 0.f;
        }
        __syncthreads();

        #pragma unroll
        for (int cil = 0; cil < CICHUNK; cil++) {
            float tap[16];
            #pragma unroll
            for (int ky = 0; ky < 4; ky++)
                #pragma unroll
                for (int kx = 0; kx < 4; kx++)
                    tap[ky * 4 + kx] = tile[cil][2 * ly + ky][2 * lx + kx];
            #pragma unroll
            for (int k = 0; k < 16; k++) {
                const float tv = tap[k];
                const float4* w4 = (const float4*)&ws[(cil * 16 + k) * COUTG];
                #pragma unroll
                for (int j4 = 0; j4 < COUTG / 4; j4++) {
                    const float4 ww = w4[j4];
                    acc[4*j4+0] = fmaf(tv, ww.x, acc[4*j4+0]);
                    acc[4*j4+1] = fmaf(tv, ww.y, acc[4*j4+1]);
                    acc[4*j4+2] = fmaf(tv, ww.z, acc[4*j4+2]);
                    acc[4*j4+3] = fmaf(tv, ww.w, acc[4*j4+3]);
                }
            }
        }
    }

    const int oy = ty * 16 + ly, ox = tx * 16 + lx;
    #pragma unroll
    for (int j = 0; j < COUTG; j++)
        out[(((long long)n * COUT + cog + j) * HOUT + oy) * WOUT + ox] = acc[j];
}

// --------------------------- deconv k4 s2 p1 -------------------------------
// Block = 16x16 quads (32x32 output). Input patch 18x18 per channel in smem.
// Weight (ky,kx) -> output parity (ky&1,kx&1), patch offset r=(ky>>1)+(ky&1).
template <int CIN, int COUT, int COUTG, int COUTG_PAD, int CICHUNK, int HIN, int WIN>
__global__ __launch_bounds__(256)
void deconv_t(const float* __restrict__ in, const float* __restrict__ w,
              const float* __restrict__ bias, float* __restrict__ out)
{
    constexpr int HOUT = HIN * 2, WOUT = WIN * 2;
    constexpr int NBX = WIN / 16, NBY = HIN / 16;
    constexpr int TIN = 18, TP = 20;

    __shared__ float tile[CICHUNK][TIN][TP];
    __shared__ __align__(16) float ws[CICHUNK * 16 * COUTG_PAD];

    const int b  = blockIdx.x;
    const int tx = b % NBX;
    const int ty = (b / NBX) % NBY;
    const int n  = b / (NBX * NBY);
    const int cog = blockIdx.y * COUTG;
    const int lx = threadIdx.x & 15, ly = threadIdx.x >> 4;

    const int X0 = tx * 16 - 1, Y0 = ty * 16 - 1;
    const float* inn = in + (long long)n * CIN * HIN * WIN;

    float acc[4][COUTG_PAD];
    #pragma unroll
    for (int j = 0; j < COUTG_PAD; j++) {
        const float bv = (cog + j < COUT) ? __ldg(&bias[cog + j]) : 0.f;
        acc[0][j] = bv; acc[1][j] = bv; acc[2][j] = bv; acc[3][j] = bv;
    }

    for (int ci0 = 0; ci0 < CIN; ci0 += CICHUNK) {
        __syncthreads();
        for (int t = threadIdx.x; t < COUTG_PAD * CICHUNK * 16; t += 256) {
            const int j  = t % COUTG_PAD;
            const int kk = t / COUTG_PAD;
            ws[t] = (cog + j < COUT) ? w[(cog + j) * CIN * 16 + ci0 * 16 + kk] : 0.f;
        }
        for (int t = threadIdx.x; t < CICHUNK * TIN * TIN; t += 256) {
            const int c  = t / (TIN * TIN);
            const int r  = (t / TIN) % TIN;
            const int cc = t % TIN;
            const int gy = Y0 + r, gx = X0 + cc;
            const bool ok = ((unsigned)gy < (unsigned)HIN) &&
                            ((unsigned)gx < (unsigned)WIN);
            tile[c][r][cc] = ok ?
                __ldg(&inn[((long long)(ci0 + c) * HIN + gy) * WIN + gx]) : 0.f;
        }
        __syncthreads();

        #pragma unroll
        for (int cil = 0; cil < CICHUNK; cil++) {
            float tv[3][3];
            #pragma unroll
            for (int r = 0; r < 3; r++)
                #pragma unroll
                for (int c = 0; c < 3; c++)
                    tv[r][c] = tile[cil][ly + r][lx + c];
            #pragma unroll
            for (int ky = 0; ky < 4; ky++) {
                #pragma unroll
                for (int kx = 0; kx < 4; kx++) {
                    const int py = ky & 1, px = kx & 1;
                    const float t = tv[(ky >> 1) + py][(kx >> 1) + px];
                    const int o = py * 2 + px;
                    const float4* w4 =
                        (const float4*)&ws[(cil * 16 + ky * 4 + kx) * COUTG_PAD];
                    #pragma unroll
                    for (int j4 = 0; j4 < COUTG_PAD / 4; j4++) {
                        const float4 ww = w4[j4];
                        acc[o][4*j4+0] = fmaf(t, ww.x, acc[o][4*j4+0]);
                        acc[o][4*j4+1] = fmaf(t, ww.y, acc[o][4*j4+1]);
                        acc[o][4*j4+2] = fmaf(t, ww.z, acc[o][4*j4+2]);
                        acc[o][4*j4+3] = fmaf(t, ww.w, acc[o][4*j4+3]);
                    }
                }
            }
        }
    }

    const int Y = ty * 16 + ly, X = tx * 16 + lx;
    #pragma unroll
    for (int j = 0; j < COUTG; j++) {
        const long long cb = (long long)n * COUT + cog + j;
        float2* row0 = (float2*)out + (cb * HOUT + 2 * Y) * (WOUT / 2) + X;
        float2* row1 = (float2*)out + (cb * HOUT + 2 * Y + 1) * (WOUT / 2) + X;
        *row0 = make_float2(acc[0][j], acc[1][j]);
        *row1 = make_float2(acc[2][j], acc[3][j]);
    }
}

// ------------------------------- batchnorm ---------------------------------
__global__ __launch_bounds__(256)
void bn_stats(const float* __restrict__ x, int C, int HW)
{
    const int c = blockIdx.x >> 5;
    const int s = blockIdx.x & 31;
    const int chunk4 = HW >> 7;

    float sum = 0.f, sq = 0.f;
    for (int n = 0; n < BB; n++) {
        const float4* base = (const float4*)(x + ((long long)(n * C + c)) * HW) +
                             s * chunk4;
        for (int p = threadIdx.x; p < chunk4; p += 256) {
            float4 v = base[p];
            sum += v.x + v.y + v.z + v.w;
            sq = fmaf(v.x, v.x, sq); sq = fmaf(v.y, v.y, sq);
            sq = fmaf(v.z, v.z, sq); sq = fmaf(v.w, v.w, sq);
        }
    }
    __shared__ float s1[256], s2[256];
    s1[threadIdx.x] = sum; s2[threadIdx.x] = sq;
    __syncthreads();
    for (int off = 128; off; off >>= 1) {
        if (threadIdx.x < off) {
            s1[threadIdx.x] += s1[threadIdx.x + off];
            s2[threadIdx.x] += s2[threadIdx.x + off];
        }
        __syncthreads();
    }
    if (threadIdx.x == 0) g_part[blockIdx.x] = make_float2(s1[0], s2[0]);
}

__global__ void bn_finalize(const float* __restrict__ gam,
                            const float* __restrict__ bet, int HW)
{
    const int c = blockIdx.x;
    float2 p = g_part[c * 32 + threadIdx.x];
    double S = p.x, Q = p.y;
    for (int off = 16; off; off >>= 1) {
        S += __shfl_down_sync(0xffffffffu, S, off);
        Q += __shfl_down_sync(0xffffffffu, Q, off);
    }
    if (threadIdx.x == 0) {
        const double P = (double)BB * (double)HW;
        const double mean = S / P;
        const double var  = Q / P - mean * mean;
        const float rstd  = (float)(1.0 / sqrt(var + (double)BN_EPS));
        const float sc = gam[c] * rstd;
        g_scale[c] = sc;
        g_shift[c] = bet[c] - (float)mean * sc;
    }
}

template <int MODE>
__global__ __launch_bounds__(256)
void bn_apply(float* __restrict__ x, int C, int HW, int total4)
{
    const int i = blockIdx.x * 256 + threadIdx.x;
    if (i >= total4) return;
    const int hw4 = HW >> 2;
    const int c = (i / hw4) % C;
    const float sc = g_scale[c], sh = g_shift[c];
    float4 v = ((float4*)x)[i];
    v.x = fmaf(v.x, sc, sh); v.y = fmaf(v.y, sc, sh);
    v.z = fmaf(v.z, sc, sh); v.w = fmaf(v.w, sc, sh);
    if (MODE == 0) {
        v.x = fmaxf(v.x, 0.f); v.y = fmaxf(v.y, 0.f);
        v.z = fmaxf(v.z, 0.f); v.w = fmaxf(v.w, 0.f);
    } else {
        v.x = tanhf(v.x); v.y = tanhf(v.y);
        v.z = tanhf(v.z); v.w = tanhf(v.w);
    }
    ((float4*)x)[i] = v;
}

// ---------------------------------- VQ -------------------------------------
__global__ void code_norms(const float* __restrict__ cb)
{
    const int k = threadIdx.x;
    float s = 0.f;
    const float* r = cb + k * 64;
    #pragma unroll
    for (int d = 0; d < 64; d++) s = fmaf(r[d], r[d], s);
    g_codeNorm[k] = s;
}

__global__ __launch_bounds__(128)
void vq_argmin(const float* __restrict__ ze, const float* __restrict__ cb)
{
    __shared__ float sc[64 * 64];
    __shared__ float scn[64];
    __shared__ float red[128];

    const int idx = blockIdx.x * 128 + threadIdx.x;
    const int n  = idx >> 10;
    const int hw = idx & 1023;
    const float* base = ze + (long long)n * 64 * 1024 + hw;

    float z[64];
    #pragma unroll
    for (int d = 0; d < 64; d++) z[d] = base[d * 1024];
    float zz = 0.f;
    #pragma unroll
    for (int d = 0; d < 64; d++) zz = fmaf(z[d], z[d], zz);

    float best = 3.4e38f;
    int   bi   = 0;
    for (int ch = 0; ch < 8; ch++) {
        __syncthreads();
        for (int t = threadIdx.x; t < 1024; t += 128)
            ((float4*)sc)[t] = ((const float4*)(cb + ch * 4096))[t];
        if (threadIdx.x < 64) scn[threadIdx.x] = g_codeNorm[ch * 64 + threadIdx.x];
        __syncthreads();
        #pragma unroll 2
        for (int j = 0; j < 64; j++) {
            const float4* cp = (const float4*)&sc[j * 64];
            float dot = 0.f;
            #pragma unroll
            for (int d4 = 0; d4 < 16; d4++) {
                float4 c4 = cp[d4];
                dot = fmaf(z[4*d4+0], c4.x, dot);
                dot = fmaf(z[4*d4+1], c4.y, dot);
                dot = fmaf(z[4*d4+2], c4.z, dot);
                dot = fmaf(z[4*d4+3], c4.w, dot);
            }
            const float dist = zz - 2.f * dot + scn[j];
            const int k = ch * 64 + j;
            if (dist < best) { best = dist; bi = k; }
        }
    }
    g_idx[idx] = bi;

    const float* cr = cb + bi * 64;
    float e = 0.f;
    #pragma unroll
    for (int d = 0; d < 64; d++) { float df = z[d] - cr[d]; e = fmaf(df, df, e); }

    red[threadIdx.x] = e;
    __syncthreads();
    for (int off = 64; off; off >>= 1) {
        if (threadIdx.x < off) red[threadIdx.x] += red[threadIdx.x + off];
        __syncthreads();
    }
    if (threadIdx.x == 0) g_lossPart[blockIdx.x] = red[0];
}

__global__ void vq_loss_final(float* __restrict__ loss_out)
{
    __shared__ double red[512];
    red[threadIdx.x] = (double)g_lossPart[threadIdx.x];
    __syncthreads();
    for (int off = 256; off; off >>= 1) {
        if (threadIdx.x < off) red[threadIdx.x] += red[threadIdx.x + off];
        __syncthreads();
    }
    if (threadIdx.x == 0)
        loss_out[0] = (float)(2.0 * red[0] / (65536.0 * 64.0));
}

__global__ __launch_bounds__(256)
void vq_scatter(float* __restrict__ q, const float* __restrict__ cb)
{
    const int i = blockIdx.x * 256 + threadIdx.x;
    const int hw = i & 1023;
    const int d  = (i >> 10) & 63;
    const int n  = i >> 16;
    const int code = g_idx[n * 1024 + hw];
    q[i] = cb[code * 64 + d];
}

// -------------------------------- launch -----------------------------------
static inline int nblk(long long total) { return (int)((total + 255) / 256); }

extern "C" void kernel_launch(void* const* d_in, const int* in_sizes, int n_in,
                              void* d_out, int out_size)
{
    (void)in_sizes; (void)n_in;
    const float* x    = (const float*)d_in[0];
    const float* cb   = (const float*)d_in[1];
    const float* eW1  = (const float*)d_in[2];
    const float* eb1  = (const float*)d_in[3];
    const float* eg1  = (const float*)d_in[4];
    const float* ebt1 = (const float*)d_in[5];
    const float* eW2  = (const float*)d_in[6];
    const float* eb2  = (const float*)d_in[7];
    const float* eg2  = (const float*)d_in[8];
    const float* ebt2 = (const float*)d_in[9];
    const float* eW3  = (const float*)d_in[10];
    const float* eb3  = (const float*)d_in[11];
    const float* eg3  = (const float*)d_in[12];
    const float* ebt3 = (const float*)d_in[13];
    const float* dW1  = (const float*)d_in[14];
    const float* db1  = (const float*)d_in[15];
    const float* dg1  = (const float*)d_in[16];
    const float* dbt1 = (const float*)d_in[17];
    const float* dW2  = (const float*)d_in[18];
    const float* db2  = (const float*)d_in[19];
    const float* dg2  = (const float*)d_in[20];
    const float* dbt2 = (const float*)d_in[21];
    const float* dW3  = (const float*)d_in[22];
    const float* db3  = (const float*)d_in[23];
    const float* dg3  = (const float*)d_in[24];
    const float* dbt3 = (const float*)d_in[25];
    float* out = (float*)d_out;

    float *a1, *a2, *a3, *q, *d1, *d2;
    cudaGetSymbolAddress((void**)&a1, g_a1);
    cudaGetSymbolAddress((void**)&a2, g_a2);
    cudaGetSymbolAddress((void**)&a3, g_a3);
    cudaGetSymbolAddress((void**)&q,  g_q);
    cudaGetSymbolAddress((void**)&d1, g_d1);
    cudaGetSymbolAddress((void**)&d2, g_d2);

    // ---------------- encoder ----------------
    {   // conv1: 3->16, 256->128. tiles: 8x8 x 64 images = 4096 blocks
        const long long T = (long long)BB * 16 * 128 * 128;
        dim3 grid(4096, 1);
        conv_t<3, 16, 16, 3, 256, 256><<<grid, 256>>>(x, eW1, eb1, a1);
        bn_stats<<<16 * 32, 256>>>(a1, 16, 128 * 128);
        bn_finalize<<<16, 32>>>(eg1, ebt1, 128 * 128);
        bn_apply<0><<<nblk(T / 4), 256>>>(a1, 16, 128 * 128, (int)(T / 4));
    }
    {   // conv2: 16->32, 128->64. tiles: 4x4 x 64 = 1024 blocks
        const long long T = (long long)BB * 32 * 64 * 64;
        dim3 grid(1024, 1);
        conv_t<16, 32, 32, 4, 128, 128><<<grid, 256>>>(a1, eW2, eb2, a2);
        bn_stats<<<32 * 32, 256>>>(a2, 32, 64 * 64);
        bn_finalize<<<32, 32>>>(eg2, ebt2, 64 * 64);
        bn_apply<0><<<nblk(T / 4), 256>>>(a2, 32, 64 * 64, (int)(T / 4));
    }
    {   // conv3: 32->64, 64->32. tiles: 2x2 x 64 = 256 blocks, 2 co-groups
        const long long T = (long long)BB * 64 * 32 * 32;
        dim3 grid(256, 2);
        conv_t<32, 64, 32, 4, 64, 64><<<grid, 256>>>(a2, eW3, eb3, a3);
        bn_stats<<<64 * 32, 256>>>(a3, 64, 32 * 32);
        bn_finalize<<<64, 32>>>(eg3, ebt3, 32 * 32);
        bn_apply<0><<<nblk(T / 4), 256>>>(a3, 64, 32 * 32, (int)(T / 4));
    }

    // ---------------- vector quantization ----------------
    code_norms<<<1, 512>>>(cb);
    vq_argmin<<<512, 128>>>(a3, cb);
    vq_loss_final<<<1, 512>>>(out + (out_size - 1));
    vq_scatter<<<nblk((long long)BB * 64 * 32 * 32), 256>>>(q, cb);

    // ---------------- decoder ----------------
    {   // deconv1: 64->32. quad tiles: 2x2 x 64 = 256 blocks, 2 co-groups
        const long long T = (long long)BB * 32 * 64 * 64;
        dim3 grid(256, 2);
        deconv_t<64, 32, 16, 16, 8, 32, 32><<<grid, 256>>>(q, dW1, db1, d1);
        bn_stats<<<32 * 32, 256>>>(d1, 32, 64 * 64);
        bn_finalize<<<32, 32>>>(dg1, dbt1, 64 * 64);
        bn_apply<0><<<nblk(T / 4), 256>>>(d1, 32, 64 * 64, (int)(T / 4));
    }
    {   // deconv2: 32->16. quad tiles: 4x4 x 64 = 1024 blocks
        const long long T = (long long)BB * 16 * 128 * 128;
        dim3 grid(1024, 1);
        deconv_t<32, 16, 16, 16, 8, 64, 64><<<grid, 256>>>(d1, dW2, db2, d2);
        bn_stats<<<16 * 32, 256>>>(d2, 16, 128 * 128);
        bn_finalize<<<16, 32>>>(dg2, dbt2, 128 * 128);
        bn_apply<0><<<nblk(T / 4), 256>>>(d2, 16, 128 * 128, (int)(T / 4));
    }
    {   // deconv3: 16->3 (pad 4). quad tiles: 8x8 x 64 = 4096 blocks
        const long long T = (long long)BB * 3 * 256 * 256;
        dim3 grid(4096, 1);
        deconv_t<16, 3, 3, 4, 16, 128, 128><<<grid, 256>>>(d2, dW3, db3, out);
        bn_stats<<<3 * 32, 256>>>(out, 3, 256 * 256);
        bn_finalize<<<3, 32>>>(dg3, dbt3, 256 * 256);
        bn_apply<1><<<nblk(T / 4), 256>>>(out, 3, 256 * 256, (int)T / 4);
    }
}